// round 13
// baseline (speedup 1.0000x reference)
#include <cuda_runtime.h>
#include <cuda_bf16.h>
#include <cstdint>

#define BB 16
#define CC 16
#define PP 512
#define DD 256

typedef __nv_bfloat16  bf16;
typedef __nv_bfloat162 bf162;

// Scratch (allocation-free rule: __device__ globals)
__device__ bf16  g_qb  [BB*CC*PP*DD];   // 67 MB  bf16(query)
__device__ bf16  g_ctxb[BB*CC*PP*DD];   // 67 MB  bf16(context)
__device__ bf16  g_wt  [3*CC*DD*DD];    // 6.3 MB transposed weights [e][d]
__device__ bf16  g_q   [BB*CC*PP*DD];   // 67 MB
__device__ bf16  g_k   [BB*CC*PP*DD];   // 67 MB
__device__ bf16  g_v   [BB*CC*PP*DD];   // 67 MB
__device__ bf16  g_vt  [BB*CC*PP*DD];   // 67 MB  V^T [e][q]
__device__ float g_sc  [BB*CC*PP*PP];   // 268 MB scores fp32
__device__ bf16  g_pb  [BB*CC*PP*PP];   // 134 MB probs bf16

// ---------------------------------------------------------------------------
// helpers
// ---------------------------------------------------------------------------
__device__ __forceinline__ void mma16(float* c, const uint32_t* a, const uint32_t* b) {
    asm volatile(
        "mma.sync.aligned.m16n8k16.row.col.f32.bf16.bf16.f32 "
        "{%0,%1,%2,%3}, {%4,%5,%6,%7}, {%8,%9}, {%0,%1,%2,%3};"
        : "+f"(c[0]), "+f"(c[1]), "+f"(c[2]), "+f"(c[3])
        : "r"(a[0]), "r"(a[1]), "r"(a[2]), "r"(a[3]), "r"(b[0]), "r"(b[1]));
}

__device__ __forceinline__ void ldsm4(uint32_t* r, uint32_t addr) {
    asm volatile("ldmatrix.sync.aligned.m8n8.x4.shared.b16 {%0,%1,%2,%3}, [%4];"
        : "=r"(r[0]), "=r"(r[1]), "=r"(r[2]), "=r"(r[3]) : "r"(addr));
}

__device__ __forceinline__ void cpa16(uint32_t dst, const void* src) {
    asm volatile("cp.async.cg.shared.global [%0], [%1], 16;" :: "r"(dst), "l"(src));
}
#define CP_COMMIT() asm volatile("cp.async.commit_group;")
#define CP_WAIT0()  asm volatile("cp.async.wait_group 0;")
#define CP_WAIT1()  asm volatile("cp.async.wait_group 1;")

__device__ __forceinline__ uint32_t s2u(const void* p) {
    return (uint32_t)__cvta_generic_to_shared(p);
}

__device__ __forceinline__ uint32_t pack_bf(float lo, float hi) {
    bf162 h = __float22bfloat162_rn(make_float2(lo, hi));
    return *(uint32_t*)&h;
}

// ---------------------------------------------------------------------------
// Shared bf16 GEMM mainloop: C[128,128] tile, Kc=64, 3-stage cp.async pipeline
// with prefetch distance 2 (chunks ch+1, ch+2 in flight during compute of ch).
// A: [m][k] k-contig (lda), B: [n][k] k-contig (ldb). 256 threads, 8 warps 64x32.
// smem rows padded to 72 bf16 (144B): row stride 36 words == 4 mod 32 ->
// LDSM 8-row groups hit word offsets {0,4,...,28}: conflict-free ldmatrix.
// ---------------------------------------------------------------------------
template<int KTOT>
__device__ __forceinline__ void gemm_bf16(
    const bf16* __restrict__ A, int lda,
    const bf16* __restrict__ B, int ldb,
    int m0, int n0, char* smemraw, float acc[4][4][4])
{
    bf16 (*As)[128][72] = (bf16 (*)[128][72])smemraw;
    bf16 (*Bs)[128][72] = (bf16 (*)[128][72])(smemraw + 3*128*72*2);

    int t = threadIdx.x;
    int lane = t & 31, wid = t >> 5;
    int wm = wid >> 2, wn = wid & 3;

    int lr = lane & 15;            // ldmatrix row within 16-row group
    int lc = (lane >> 4) * 8;      // ldmatrix k-chunk (0 or 8 bf16)

    int rA = t >> 3, c8 = (t & 7) * 8;   // global->smem: 128 rows x 64 bf16, 16B units

    const int NCH = KTOT / 64;     // >= 2 for all call sites

    // prologue: issue chunks 0 and 1 as separate groups
#pragma unroll
    for (int pc = 0; pc < 2; pc++) {
        int k0 = pc * 64;
#pragma unroll
        for (int i = 0; i < 4; i++)
            cpa16(s2u(&As[pc][rA + 32*i][c8]), A + (size_t)(m0 + rA + 32*i)*lda + k0 + c8);
#pragma unroll
        for (int i = 0; i < 4; i++)
            cpa16(s2u(&Bs[pc][rA + 32*i][c8]), B + (size_t)(n0 + rA + 32*i)*ldb + k0 + c8);
        CP_COMMIT();
    }

    for (int ch = 0; ch < NCH; ch++) {
        // chunk ch must have landed; keep at most 1 younger group pending here
        if (ch + 1 < NCH) { CP_WAIT1(); } else { CP_WAIT0(); }
        __syncthreads();

        // prefetch chunk ch+2 into buf (ch+2)%3 == (ch-1)%3 (freed by the
        // barrier above: all warps finished compute(ch-1) before arriving)
        if (ch + 2 < NCH) {
            int k0 = (ch + 2) * 64;
            int nb = (ch + 2) % 3;
#pragma unroll
            for (int i = 0; i < 4; i++)
                cpa16(s2u(&As[nb][rA + 32*i][c8]), A + (size_t)(m0 + rA + 32*i)*lda + k0 + c8);
#pragma unroll
            for (int i = 0; i < 4; i++)
                cpa16(s2u(&Bs[nb][rA + 32*i][c8]), B + (size_t)(n0 + rA + 32*i)*ldb + k0 + c8);
            CP_COMMIT();
        }

        int cur = ch % 3;
        uint32_t aBase[4], bBase[2];
#pragma unroll
        for (int mt = 0; mt < 4; mt++)
            aBase[mt] = s2u(&As[cur][wm*64 + mt*16 + lr][lc]);
#pragma unroll
        for (int np = 0; np < 2; np++)
            bBase[np] = s2u(&Bs[cur][wn*32 + np*16 + lr][lc]);

#pragma unroll
        for (int kt = 0; kt < 64; kt += 16) {
            uint32_t af[4][4], bm[2][4];
#pragma unroll
            for (int mt = 0; mt < 4; mt++)
                ldsm4(af[mt], aBase[mt] + kt*2);
#pragma unroll
            for (int np = 0; np < 2; np++)
                ldsm4(bm[np], bBase[np] + kt*2);
            // bm[np] = {nt(2np).b0, nt(2np+1).b0, nt(2np).b1, nt(2np+1).b1}
#pragma unroll
            for (int mt = 0; mt < 4; mt++) {
#pragma unroll
                for (int nt = 0; nt < 4; nt++) {
                    uint32_t bfr[2] = { bm[nt>>1][nt & 1], bm[nt>>1][(nt & 1) + 2] };
                    mma16(acc[mt][nt], af[mt], bfr);
                }
            }
        }
        __syncthreads();
    }
}

static const int GEMM_SMEM = 3*128*72*2 * 2;   // 110592 B (2 CTAs/SM: 221 KB)

// ---------------------------------------------------------------------------
// Kernel 0: weight transpose+convert: W[c][d][e] fp32 -> g_wt[type][c][e][d] bf16
// ---------------------------------------------------------------------------
__global__ void wt_kernel(const float* __restrict__ wq,
                          const float* __restrict__ wk,
                          const float* __restrict__ wv) {
    __shared__ float s[32][33];
    int z = blockIdx.z;
    int type = z / CC, c = z % CC;
    const float* W = (type == 0 ? wq : (type == 1 ? wk : wv)) + (size_t)c*DD*DD;
    bf16* O = g_wt + (size_t)(type*CC + c)*DD*DD;
    int d0 = blockIdx.y * 32, e0 = blockIdx.x * 32;
    int tx = threadIdx.x, ty = threadIdx.y;
#pragma unroll
    for (int j = 0; j < 4; j++)
        s[ty + 8*j][tx] = W[(d0 + ty + 8*j)*DD + e0 + tx];
    __syncthreads();
#pragma unroll
    for (int j = 0; j < 4; j++)
        O[(e0 + ty + 8*j)*DD + d0 + tx] = __float2bfloat16(s[tx][ty + 8*j]);
}

// ---------------------------------------------------------------------------
// Kernel 1: context + bf16 conversions of query and context
// ---------------------------------------------------------------------------
__global__ void ctx_kernel(const float* __restrict__ query,
                           const float* __restrict__ aw) {
    int idx = blockIdx.x * blockDim.x + threadIdx.x;  // over B*P*D
    if (idx >= BB*PP*DD) return;
    int d = idx % DD;
    int p = (idx / DD) % PP;
    int b = idx / (PP*DD);

    float vals[CC];
    float sum = 0.f;
#pragma unroll
    for (int c = 0; c < CC; c++) {
        int ii = ((b*CC + c)*PP + p)*DD + d;
        float qv = query[ii];
        float v  = aw[(c*PP + p)*DD + d] * qv;
        vals[c] = v;
        sum += v;
        g_qb[ii] = __float2bfloat16(qv);
    }
#pragma unroll
    for (int c = 0; c < CC; c++) {
        g_ctxb[((b*CC + c)*PP + p)*DD + d] = __float2bfloat16(sum - vals[c]);
    }
}

// ---------------------------------------------------------------------------
// Kernel 2: fused q/k/v projections (bf16 MMA). out = relu(X@W+b) [*1/16 q]
// ---------------------------------------------------------------------------
__global__ void __launch_bounds__(256, 2) proj_bf(const float* __restrict__ bq,
                                                  const float* __restrict__ bk,
                                                  const float* __restrict__ bv) {
    extern __shared__ char smem[];
    int z    = blockIdx.z;
    int type = z / (BB*CC);
    int bc   = z % (BB*CC);
    int c    = bc % CC;

    const bf16* A    = (type == 0 ? g_qb : g_ctxb) + (size_t)bc * PP * DD;
    const bf16* Bw   = g_wt + (size_t)(type*CC + c) * DD * DD;
    const float* bias = (type == 0 ? bq : (type == 1 ? bk : bv)) + c * DD;
    bf16*       out  = (type == 0 ? g_q : (type == 1 ? g_k : g_v)) + (size_t)bc * PP * DD;

    int m0 = blockIdx.y * 128;
    int n0 = blockIdx.x * 128;

    float acc[4][4][4] = {};
    gemm_bf16<DD>(A, DD, Bw, DD, m0, n0, smem, acc);

    int t = threadIdx.x;
    int lane = t & 31, wid = t >> 5;
    int wm = wid >> 2, wn = wid & 3;
    int g = lane >> 2, tg = lane & 3;
    float scale = (type == 0) ? 0.0625f : 1.0f;
#pragma unroll
    for (int mt = 0; mt < 4; mt++) {
#pragma unroll
        for (int nt = 0; nt < 4; nt++) {
            int row = m0 + wm*64 + mt*16 + g;
            int col = n0 + wn*32 + nt*8 + 2*tg;
            float b0v = bias[col], b1v = bias[col+1];
            float* o = acc[mt][nt];
            *(uint32_t*)&out[(size_t)row*DD + col] =
                pack_bf(fmaxf(o[0]+b0v, 0.f)*scale, fmaxf(o[1]+b1v, 0.f)*scale);
            *(uint32_t*)&out[(size_t)(row+8)*DD + col] =
                pack_bf(fmaxf(o[2]+b0v, 0.f)*scale, fmaxf(o[3]+b1v, 0.f)*scale);
        }
    }
}

// ---------------------------------------------------------------------------
// Kernel 3: scores = q @ k^T (bf16 in, fp32 out)
// ---------------------------------------------------------------------------
__global__ void __launch_bounds__(256, 2) scores_bf() {
    extern __shared__ char smem[];
    int bc = blockIdx.z;
    const bf16* Q = g_q + (size_t)bc * PP * DD;
    const bf16* K = g_k + (size_t)bc * PP * DD;
    float*      S = g_sc + (size_t)bc * PP * PP;

    int m0 = blockIdx.y * 128;
    int n0 = blockIdx.x * 128;

    float acc[4][4][4] = {};
    gemm_bf16<DD>(Q, DD, K, DD, m0, n0, smem, acc);

    int t = threadIdx.x;
    int lane = t & 31, wid = t >> 5;
    int wm = wid >> 2, wn = wid & 3;
    int g = lane >> 2, tg = lane & 3;
#pragma unroll
    for (int mt = 0; mt < 4; mt++) {
#pragma unroll
        for (int nt = 0; nt < 4; nt++) {
            int row = m0 + wm*64 + mt*16 + g;
            int col = n0 + wn*32 + nt*8 + 2*tg;
            float* o = acc[mt][nt];
            *(float2*)&S[(size_t)row*PP + col]     = make_float2(o[0], o[1]);
            *(float2*)&S[(size_t)(row+8)*PP + col] = make_float2(o[2], o[3]);
        }
    }
}

// ---------------------------------------------------------------------------
// Kernel 4: softmax, one warp per 512 row; fp32 in, bf16 probs out.
// ---------------------------------------------------------------------------
__global__ void softmax_warp() {
    int row  = blockIdx.x * 8 + (threadIdx.x >> 5);
    int lane = threadIdx.x & 31;
    const float* r = g_sc + (size_t)row * PP;
    bf16* pb = g_pb + (size_t)row * PP;

    float4 v[4];
#pragma unroll
    for (int i = 0; i < 4; i++)
        v[i] = *(const float4*)(r + (i*32 + lane)*4);

    float m = -1e30f;
#pragma unroll
    for (int i = 0; i < 4; i++)
        m = fmaxf(m, fmaxf(fmaxf(v[i].x, v[i].y), fmaxf(v[i].z, v[i].w)));
#pragma unroll
    for (int o = 16; o; o >>= 1) m = fmaxf(m, __shfl_xor_sync(0xffffffffu, m, o));

    float s = 0.f;
#pragma unroll
    for (int i = 0; i < 4; i++) {
        v[i].x = __expf(v[i].x - m);
        v[i].y = __expf(v[i].y - m);
        v[i].z = __expf(v[i].z - m);
        v[i].w = __expf(v[i].w - m);
        s += v[i].x + v[i].y + v[i].z + v[i].w;
    }
#pragma unroll
    for (int o = 16; o; o >>= 1) s += __shfl_xor_sync(0xffffffffu, s, o);

    float inv = 1.f / s;
#pragma unroll
    for (int i = 0; i < 4; i++) {
        uint2 u;
        u.x = pack_bf(v[i].x * inv, v[i].y * inv);
        u.y = pack_bf(v[i].z * inv, v[i].w * inv);
        *(uint2*)(pb + (i*32 + lane)*4) = u;
    }
}

// ---------------------------------------------------------------------------
// Kernel 5: V transpose: g_v [p][e] bf16 -> g_vt [e][p] bf16 per (b,c)
// ---------------------------------------------------------------------------
__global__ void vt_kernel() {
    __shared__ bf16 s[32][34];
    int bc = blockIdx.z;
    const bf16* V = g_v  + (size_t)bc * PP * DD;
    bf16*       O = g_vt + (size_t)bc * DD * PP;
    int p0 = blockIdx.y * 32, e0 = blockIdx.x * 32;
    int tx = threadIdx.x, ty = threadIdx.y;
#pragma unroll
    for (int j = 0; j < 4; j++)
        s[ty + 8*j][tx] = V[(size_t)(p0 + ty + 8*j)*DD + e0 + tx];
    __syncthreads();
#pragma unroll
    for (int j = 0; j < 4; j++)
        O[(size_t)(e0 + ty + 8*j)*PP + p0 + tx] = s[tx][ty + 8*j];
}

// ---------------------------------------------------------------------------
// Kernel 6: out = probs @ v (bf16 in, fp32 out). M=512, K=512, N=256.
// ---------------------------------------------------------------------------
__global__ void __launch_bounds__(256, 2) av_bf(float* __restrict__ out) {
    extern __shared__ char smem[];
    int bc = blockIdx.z;
    const bf16* A = g_pb + (size_t)bc * PP * PP;   // [p][q], ld PP
    const bf16* B = g_vt + (size_t)bc * DD * PP;   // [e][q], ld PP
    float*      O = out  + (size_t)bc * PP * DD;

    int m0 = blockIdx.y * 128;
    int n0 = blockIdx.x * 128;

    float acc[4][4][4] = {};
    gemm_bf16<PP>(A, PP, B, PP, m0, n0, smem, acc);

    int t = threadIdx.x;
    int lane = t & 31, wid = t >> 5;
    int wm = wid >> 2, wn = wid & 3;
    int g = lane >> 2, tg = lane & 3;
#pragma unroll
    for (int mt = 0; mt < 4; mt++) {
#pragma unroll
        for (int nt = 0; nt < 4; nt++) {
            int row = m0 + wm*64 + mt*16 + g;
            int col = n0 + wn*32 + nt*8 + 2*tg;
            float* o = acc[mt][nt];
            *(float2*)&O[(size_t)row*DD + col]     = make_float2(o[0], o[1]);
            *(float2*)&O[(size_t)(row+8)*DD + col] = make_float2(o[2], o[3]);
        }
    }
}

// ---------------------------------------------------------------------------
extern "C" void kernel_launch(void* const* d_in, const int* in_sizes, int n_in,
                              void* d_out, int out_size) {
    (void)in_sizes; (void)n_in; (void)out_size;
    const float* query = (const float*)d_in[0];
    const float* aw    = (const float*)d_in[1];
    const float* wq    = (const float*)d_in[2];
    const float* wk    = (const float*)d_in[3];
    const float* wv    = (const float*)d_in[4];
    const float* bq    = (const float*)d_in[5];
    const float* bk    = (const float*)d_in[6];
    const float* bv    = (const float*)d_in[7];
    float* out = (float*)d_out;

    cudaFuncSetAttribute(proj_bf,   cudaFuncAttributeMaxDynamicSharedMemorySize, GEMM_SMEM);
    cudaFuncSetAttribute(scores_bf, cudaFuncAttributeMaxDynamicSharedMemorySize, GEMM_SMEM);
    cudaFuncSetAttribute(av_bf,     cudaFuncAttributeMaxDynamicSharedMemorySize, GEMM_SMEM);

    wt_kernel<<<dim3(8, 8, 3*CC), dim3(32, 8)>>>(wq, wk, wv);
    int n_ctx = BB*PP*DD;
    ctx_kernel<<<(n_ctx + 255)/256, 256>>>(query, aw);
    proj_bf<<<dim3(DD/128, PP/128, 3*BB*CC), 256, GEMM_SMEM>>>(bq, bk, bv);
    scores_bf<<<dim3(PP/128, PP/128, BB*CC), 256, GEMM_SMEM>>>();
    softmax_warp<<<BB*CC*PP/8, 256>>>();
    vt_kernel<<<dim3(DD/32, PP/32, BB*CC), dim3(32, 8)>>>();
    av_bf<<<dim3(DD/128, PP/128, BB*CC), 256, GEMM_SMEM>>>(out);
}

// round 14
// speedup vs baseline: 1.0630x; 1.0630x over previous
#include <cuda_runtime.h>
#include <cuda_bf16.h>
#include <cstdint>

#define BB 16
#define CC 16
#define PP 512
#define DD 256

typedef __nv_bfloat16  bf16;
typedef __nv_bfloat162 bf162;

// Scratch (allocation-free rule: __device__ globals)
__device__ bf16  g_qb  [BB*CC*PP*DD];   // bf16(query)
__device__ bf16  g_ctxb[BB*CC*PP*DD];   // bf16(context)
__device__ bf16  g_wt  [3*CC*DD*DD];    // transposed weights [e][d]
__device__ bf16  g_q   [BB*CC*PP*DD];
__device__ bf16  g_k   [BB*CC*PP*DD];
__device__ bf16  g_v   [BB*CC*PP*DD];
__device__ bf16  g_vt  [BB*CC*PP*DD];   // V^T [e][q]

// ---------------------------------------------------------------------------
// helpers
// ---------------------------------------------------------------------------
__device__ __forceinline__ void mma16(float* c, const uint32_t* a, const uint32_t* b) {
    asm volatile(
        "mma.sync.aligned.m16n8k16.row.col.f32.bf16.bf16.f32 "
        "{%0,%1,%2,%3}, {%4,%5,%6,%7}, {%8,%9}, {%0,%1,%2,%3};"
        : "+f"(c[0]), "+f"(c[1]), "+f"(c[2]), "+f"(c[3])
        : "r"(a[0]), "r"(a[1]), "r"(a[2]), "r"(a[3]), "r"(b[0]), "r"(b[1]));
}

__device__ __forceinline__ void ldsm4(uint32_t* r, uint32_t addr) {
    asm volatile("ldmatrix.sync.aligned.m8n8.x4.shared.b16 {%0,%1,%2,%3}, [%4];"
        : "=r"(r[0]), "=r"(r[1]), "=r"(r[2]), "=r"(r[3]) : "r"(addr));
}

__device__ __forceinline__ void cpa16(uint32_t dst, const void* src) {
    asm volatile("cp.async.cg.shared.global [%0], [%1], 16;" :: "r"(dst), "l"(src));
}
#define CP_COMMIT() asm volatile("cp.async.commit_group;")
#define CP_WAIT0()  asm volatile("cp.async.wait_group 0;")
#define CP_WAIT1()  asm volatile("cp.async.wait_group 1;")

__device__ __forceinline__ uint32_t s2u(const void* p) {
    return (uint32_t)__cvta_generic_to_shared(p);
}

__device__ __forceinline__ uint32_t pack_bf(float lo, float hi) {
    bf162 h = __float22bfloat162_rn(make_float2(lo, hi));
    return *(uint32_t*)&h;
}

// ---------------------------------------------------------------------------
// bf16 GEMM mainloop (proj): C[128,128], Kc=64, 2-stage cp.async (R10-best).
// A: [m][k] (lda), B: [n][k] (ldb). 256 threads, 8 warps 64x32.
// Rows padded to 72 bf16: stride 36 words == 4 mod 32 -> conflict-free LDSM.
// ---------------------------------------------------------------------------
template<int KTOT>
__device__ __forceinline__ void gemm_bf16(
    const bf16* __restrict__ A, int lda,
    const bf16* __restrict__ B, int ldb,
    int m0, int n0, char* smemraw, float acc[4][4][4])
{
    bf16 (*As)[128][72] = (bf16 (*)[128][72])smemraw;
    bf16 (*Bs)[128][72] = (bf16 (*)[128][72])(smemraw + 2*128*72*2);

    int t = threadIdx.x;
    int lane = t & 31, wid = t >> 5;
    int wm = wid >> 2, wn = wid & 3;
    int lr = lane & 15, lc = (lane >> 4) * 8;
    int rA = t >> 3, c8 = (t & 7) * 8;

    // prologue: chunk 0 -> buf 0
#pragma unroll
    for (int i = 0; i < 4; i++)
        cpa16(s2u(&As[0][rA + 32*i][c8]), A + (size_t)(m0 + rA + 32*i)*lda + c8);
#pragma unroll
    for (int i = 0; i < 4; i++)
        cpa16(s2u(&Bs[0][rA + 32*i][c8]), B + (size_t)(n0 + rA + 32*i)*ldb + c8);
    CP_COMMIT();

    const int NCH = KTOT / 64;
    for (int ch = 0; ch < NCH; ch++) {
        if (ch + 1 < NCH) {
            int k0 = (ch + 1) * 64;
            int nb = (ch + 1) & 1;
#pragma unroll
            for (int i = 0; i < 4; i++)
                cpa16(s2u(&As[nb][rA + 32*i][c8]), A + (size_t)(m0 + rA + 32*i)*lda + k0 + c8);
#pragma unroll
            for (int i = 0; i < 4; i++)
                cpa16(s2u(&Bs[nb][rA + 32*i][c8]), B + (size_t)(n0 + rA + 32*i)*ldb + k0 + c8);
            CP_COMMIT();
            CP_WAIT1();
        } else {
            CP_WAIT0();
        }
        __syncthreads();

        int cur = ch & 1;
        uint32_t aBase[4], bBase[2];
#pragma unroll
        for (int mt = 0; mt < 4; mt++)
            aBase[mt] = s2u(&As[cur][wm*64 + mt*16 + lr][lc]);
#pragma unroll
        for (int np = 0; np < 2; np++)
            bBase[np] = s2u(&Bs[cur][wn*32 + np*16 + lr][lc]);

#pragma unroll
        for (int kt = 0; kt < 64; kt += 16) {
            uint32_t af[4][4], bm[2][4];
#pragma unroll
            for (int mt = 0; mt < 4; mt++) ldsm4(af[mt], aBase[mt] + kt*2);
#pragma unroll
            for (int np = 0; np < 2; np++) ldsm4(bm[np], bBase[np] + kt*2);
#pragma unroll
            for (int mt = 0; mt < 4; mt++)
#pragma unroll
                for (int nt = 0; nt < 4; nt++) {
                    uint32_t bfr[2] = { bm[nt>>1][nt & 1], bm[nt>>1][(nt & 1) + 2] };
                    mma16(acc[mt][nt], af[mt], bfr);
                }
        }
        __syncthreads();
    }
}

static const int GEMM_SMEM = 2*128*72*2 * 2;   // 73728 B

// ---------------------------------------------------------------------------
// Kernel 0: weight transpose+convert
// ---------------------------------------------------------------------------
__global__ void wt_kernel(const float* __restrict__ wq,
                          const float* __restrict__ wk,
                          const float* __restrict__ wv) {
    __shared__ float s[32][33];
    int z = blockIdx.z;
    int type = z / CC, c = z % CC;
    const float* W = (type == 0 ? wq : (type == 1 ? wk : wv)) + (size_t)c*DD*DD;
    bf16* O = g_wt + (size_t)(type*CC + c)*DD*DD;
    int d0 = blockIdx.y * 32, e0 = blockIdx.x * 32;
    int tx = threadIdx.x, ty = threadIdx.y;
#pragma unroll
    for (int j = 0; j < 4; j++)
        s[ty + 8*j][tx] = W[(d0 + ty + 8*j)*DD + e0 + tx];
    __syncthreads();
#pragma unroll
    for (int j = 0; j < 4; j++)
        O[(e0 + ty + 8*j)*DD + d0 + tx] = __float2bfloat16(s[tx][ty + 8*j]);
}

// ---------------------------------------------------------------------------
// Kernel 1: context + bf16 conversions
// ---------------------------------------------------------------------------
__global__ void ctx_kernel(const float* __restrict__ query,
                           const float* __restrict__ aw) {
    int idx = blockIdx.x * blockDim.x + threadIdx.x;
    if (idx >= BB*PP*DD) return;
    int d = idx % DD;
    int p = (idx / DD) % PP;
    int b = idx / (PP*DD);

    float vals[CC];
    float sum = 0.f;
#pragma unroll
    for (int c = 0; c < CC; c++) {
        int ii = ((b*CC + c)*PP + p)*DD + d;
        float qv = query[ii];
        float v  = aw[(c*PP + p)*DD + d] * qv;
        vals[c] = v;
        sum += v;
        g_qb[ii] = __float2bfloat16(qv);
    }
#pragma unroll
    for (int c = 0; c < CC; c++) {
        g_ctxb[((b*CC + c)*PP + p)*DD + d] = __float2bfloat16(sum - vals[c]);
    }
}

// ---------------------------------------------------------------------------
// Kernel 2: fused q/k/v projections
// ---------------------------------------------------------------------------
__global__ void __launch_bounds__(256, 2) proj_bf(const float* __restrict__ bq,
                                                  const float* __restrict__ bk,
                                                  const float* __restrict__ bv) {
    extern __shared__ char smem[];
    int z    = blockIdx.z;
    int type = z / (BB*CC);
    int bc   = z % (BB*CC);
    int c    = bc % CC;

    const bf16* A    = (type == 0 ? g_qb : g_ctxb) + (size_t)bc * PP * DD;
    const bf16* Bw   = g_wt + (size_t)(type*CC + c) * DD * DD;
    const float* bias = (type == 0 ? bq : (type == 1 ? bk : bv)) + c * DD;
    bf16*       out  = (type == 0 ? g_q : (type == 1 ? g_k : g_v)) + (size_t)bc * PP * DD;

    int m0 = blockIdx.y * 128;
    int n0 = blockIdx.x * 128;

    float acc[4][4][4] = {};
    gemm_bf16<DD>(A, DD, Bw, DD, m0, n0, smem, acc);

    int t = threadIdx.x;
    int lane = t & 31, wid = t >> 5;
    int wm = wid >> 2, wn = wid & 3;
    int g = lane >> 2, tg = lane & 3;
    float scale = (type == 0) ? 0.0625f : 1.0f;
#pragma unroll
    for (int mt = 0; mt < 4; mt++) {
#pragma unroll
        for (int nt = 0; nt < 4; nt++) {
            int row = m0 + wm*64 + mt*16 + g;
            int col = n0 + wn*32 + nt*8 + 2*tg;
            float b0v = bias[col], b1v = bias[col+1];
            float* o = acc[mt][nt];
            *(uint32_t*)&out[(size_t)row*DD + col] =
                pack_bf(fmaxf(o[0]+b0v, 0.f)*scale, fmaxf(o[1]+b1v, 0.f)*scale);
            *(uint32_t*)&out[(size_t)(row+8)*DD + col] =
                pack_bf(fmaxf(o[2]+b0v, 0.f)*scale, fmaxf(o[3]+b1v, 0.f)*scale);
        }
    }
}

// ---------------------------------------------------------------------------
// Kernel 3: V transpose
// ---------------------------------------------------------------------------
__global__ void vt_kernel() {
    __shared__ bf16 s[32][34];
    int bc = blockIdx.z;
    const bf16* V = g_v  + (size_t)bc * PP * DD;
    bf16*       O = g_vt + (size_t)bc * DD * PP;
    int p0 = blockIdx.y * 32, e0 = blockIdx.x * 32;
    int tx = threadIdx.x, ty = threadIdx.y;
#pragma unroll
    for (int j = 0; j < 4; j++)
        s[ty + 8*j][tx] = V[(size_t)(p0 + ty + 8*j)*DD + e0 + tx];
    __syncthreads();
#pragma unroll
    for (int j = 0; j < 4; j++)
        O[(size_t)(e0 + ty + 8*j)*PP + p0 + tx] = s[tx][ty + 8*j];
}

// ---------------------------------------------------------------------------
// Kernel 4: fused flash attention: scores + online softmax + AV.
// One CTA (512 thr, 16 warps) per (bc, 128-row m-tile). Loops 4 n-tiles of 128.
//   warp: wm = wid>>2 (rows wm*32), wq4 = wid&3 (col quarter for S / e quarter for AV)
//   S:  warp 32x32 tile  -> acc_s[2][4][4]
//   AV: warp 32x64 tile  -> acc_o[2][8][4]
// smem: Qs[128][264] resident; KV[2][256][72] streaming; Ps[128][136]; red[2][4][128]
// All strides == 4 mod 32 words -> conflict-free ldmatrix.
// ---------------------------------------------------------------------------
#define QS_OFF   0
#define KV_OFF   (128*264*2)                       // 67584
#define PS_OFF   (KV_OFF + 2*256*72*2)             // 141312
#define RED_OFF  (PS_OFF + 128*136*2)              // 176128
#define FLASH_SMEM (RED_OFF + 2*4*128*4)           // 180224

__global__ void __launch_bounds__(512, 1) flash_bf(float* __restrict__ out) {
    extern __shared__ char smem[];
    bf16 (*Qs)[264]      = (bf16 (*)[264])(smem + QS_OFF);
    bf16 (*KV)[256][72]  = (bf16 (*)[256][72])(smem + KV_OFF);
    bf16 (*Ps)[136]      = (bf16 (*)[136])(smem + PS_OFF);
    float (*red)[4][128] = (float (*)[4][128])(smem + RED_OFF);

    int bc = blockIdx.y;
    int m0 = blockIdx.x * 128;
    const bf16* Q  = g_q  + (size_t)bc * PP * DD;
    const bf16* Kp = g_k  + (size_t)bc * PP * DD;
    const bf16* Vt = g_vt + (size_t)bc * DD * PP;
    float*      O  = out  + (size_t)bc * PP * DD;

    int t = threadIdx.x;
    int lane = t & 31, wid = t >> 5;
    int wm = wid >> 2, wq4 = wid & 3;
    int g = lane >> 2, tg = lane & 3;
    int lr = lane & 15, lc = (lane >> 4) * 8;

    // load Q tile [128][256] resident (8 cpa16/thread)
#pragma unroll
    for (int i = 0; i < 8; i++) {
        int id = t + i*512;
        int row = id >> 5, cqk = (id & 31) * 8;
        cpa16(s2u(&Qs[row][cqk]), Q + (size_t)(m0 + row)*DD + cqk);
    }
    CP_COMMIT();
    CP_WAIT0();     // Q resident before mainloop (simple; one-time cost)
    __syncthreads();

    float acc_o[2][8][4] = {};
    float m_run[2][2] = {{-1e30f,-1e30f},{-1e30f,-1e30f}};
    float l_run[2][2] = {};

    for (int n0 = 0; n0 < PP; n0 += 128) {
        // ---------------- S = Q @ K^T  (K streamed, 4 e-chunks of 64) -------
        float acc_s[2][4][4] = {};
        // prologue K chunk 0 -> KV[0]
#pragma unroll
        for (int i = 0; i < 2; i++) {
            int id = t + i*512;
            int row = id >> 3, cqk = (id & 7) * 8;
            cpa16(s2u(&KV[0][row][cqk]), Kp + (size_t)(n0 + row)*DD + cqk);
        }
        CP_COMMIT();

        for (int ch = 0; ch < 4; ch++) {
            if (ch + 1 < 4) {
                int k0 = (ch + 1) * 64;
                int nb = (ch + 1) & 1;
#pragma unroll
                for (int i = 0; i < 2; i++) {
                    int id = t + i*512;
                    int row = id >> 3, cqk = (id & 7) * 8;
                    cpa16(s2u(&KV[nb][row][cqk]), Kp + (size_t)(n0 + row)*DD + k0 + cqk);
                }
                CP_COMMIT();
                CP_WAIT1();
            } else {
                CP_WAIT0();
            }
            __syncthreads();

            int cur = ch & 1;
            uint32_t aBase[2], bBase[2];
#pragma unroll
            for (int mt = 0; mt < 2; mt++)
                aBase[mt] = s2u(&Qs[wm*32 + mt*16 + lr][ch*64 + lc]);
#pragma unroll
            for (int np = 0; np < 2; np++)
                bBase[np] = s2u(&KV[cur][wq4*32 + np*16 + lr][lc]);

#pragma unroll
            for (int kt = 0; kt < 64; kt += 16) {
                uint32_t af[2][4], bm[2][4];
#pragma unroll
                for (int mt = 0; mt < 2; mt++) ldsm4(af[mt], aBase[mt] + kt*2);
#pragma unroll
                for (int np = 0; np < 2; np++) ldsm4(bm[np], bBase[np] + kt*2);
#pragma unroll
                for (int mt = 0; mt < 2; mt++)
#pragma unroll
                    for (int nt = 0; nt < 4; nt++) {
                        uint32_t bfr[2] = { bm[nt>>1][nt & 1], bm[nt>>1][(nt & 1) + 2] };
                        mma16(acc_s[mt][nt], af[mt], bfr);
                    }
            }
            __syncthreads();
        }

        // prefetch V k-chunk 0 -> KV[0] (overlaps stats phase)
#pragma unroll
        for (int i = 0; i < 4; i++) {
            int id = t + i*512;
            int row = id >> 3, cqk = (id & 7) * 8;
            cpa16(s2u(&KV[0][row][cqk]), Vt + (size_t)row*PP + n0 + cqk);
        }
        CP_COMMIT();

        // ---------------- online softmax stats ------------------------------
        float lm[2][2];
#pragma unroll
        for (int mt = 0; mt < 2; mt++) {
            float a0 = -1e30f, a1 = -1e30f;
#pragma unroll
            for (int nt = 0; nt < 4; nt++) {
                a0 = fmaxf(a0, fmaxf(acc_s[mt][nt][0], acc_s[mt][nt][1]));
                a1 = fmaxf(a1, fmaxf(acc_s[mt][nt][2], acc_s[mt][nt][3]));
            }
            lm[mt][0] = a0; lm[mt][1] = a1;
        }
#pragma unroll
        for (int mt = 0; mt < 2; mt++)
#pragma unroll
            for (int h = 0; h < 2; h++) {
                lm[mt][h] = fmaxf(lm[mt][h], __shfl_xor_sync(0xffffffffu, lm[mt][h], 1));
                lm[mt][h] = fmaxf(lm[mt][h], __shfl_xor_sync(0xffffffffu, lm[mt][h], 2));
            }
        if (tg == 0) {
#pragma unroll
            for (int mt = 0; mt < 2; mt++)
#pragma unroll
                for (int h = 0; h < 2; h++)
                    red[0][wq4][wm*32 + mt*16 + h*8 + g] = lm[mt][h];
        }
        __syncthreads();

        float scl[2][2];
#pragma unroll
        for (int mt = 0; mt < 2; mt++)
#pragma unroll
            for (int h = 0; h < 2; h++) {
                int ri = wm*32 + mt*16 + h*8 + g;
                float tm = fmaxf(fmaxf(red[0][0][ri], red[0][1][ri]),
                                 fmaxf(red[0][2][ri], red[0][3][ri]));
                float mn = fmaxf(m_run[mt][h], tm);
                scl[mt][h] = __expf(m_run[mt][h] - mn);
                m_run[mt][h] = mn;
            }
        // rescale O accumulator
#pragma unroll
        for (int mt = 0; mt < 2; mt++)
#pragma unroll
            for (int nt = 0; nt < 8; nt++) {
                acc_o[mt][nt][0] *= scl[mt][0];
                acc_o[mt][nt][1] *= scl[mt][0];
                acc_o[mt][nt][2] *= scl[mt][1];
                acc_o[mt][nt][3] *= scl[mt][1];
            }
        // exp -> P (smem) + row sums
        float ls[2][2] = {};
#pragma unroll
        for (int mt = 0; mt < 2; mt++) {
#pragma unroll
            for (int nt = 0; nt < 4; nt++) {
                float e0 = __expf(acc_s[mt][nt][0] - m_run[mt][0]);
                float e1 = __expf(acc_s[mt][nt][1] - m_run[mt][0]);
                float e2 = __expf(acc_s[mt][nt][2] - m_run[mt][1]);
                float e3 = __expf(acc_s[mt][nt][3] - m_run[mt][1]);
                int row0 = wm*32 + mt*16 + g;
                int col  = wq4*32 + nt*8 + 2*tg;
                *(uint32_t*)&Ps[row0][col]     = pack_bf(e0, e1);
                *(uint32_t*)&Ps[row0 + 8][col] = pack_bf(e2, e3);
                ls[mt][0] += e0 + e1;
                ls[mt][1] += e2 + e3;
            }
        }
#pragma unroll
        for (int mt = 0; mt < 2; mt++)
#pragma unroll
            for (int h = 0; h < 2; h++) {
                ls[mt][h] += __shfl_xor_sync(0xffffffffu, ls[mt][h], 1);
                ls[mt][h] += __shfl_xor_sync(0xffffffffu, ls[mt][h], 2);
            }
        if (tg == 0) {
#pragma unroll
            for (int mt = 0; mt < 2; mt++)
#pragma unroll
                for (int h = 0; h < 2; h++)
                    red[1][wq4][wm*32 + mt*16 + h*8 + g] = ls[mt][h];
        }
        __syncthreads();
#pragma unroll
        for (int mt = 0; mt < 2; mt++)
#pragma unroll
            for (int h = 0; h < 2; h++) {
                int ri = wm*32 + mt*16 + h*8 + g;
                float tsum = red[1][0][ri] + red[1][1][ri] + red[1][2][ri] + red[1][3][ri];
                l_run[mt][h] = l_run[mt][h] * scl[mt][h] + tsum;
            }

        // ---------------- O += P @ V  (V streamed, 2 q'-chunks of 64) -------
        // issue V k-chunk 1 -> KV[1]
#pragma unroll
        for (int i = 0; i < 4; i++) {
            int id = t + i*512;
            int row = id >> 3, cqk = (id & 7) * 8;
            cpa16(s2u(&KV[1][row][cqk]), Vt + (size_t)row*PP + n0 + 64 + cqk);
        }
        CP_COMMIT();

#pragma unroll
        for (int kc = 0; kc < 2; kc++) {
            if (kc == 0) { CP_WAIT1(); } else { CP_WAIT0(); }
            __syncthreads();   // kc data landed; also makes Ps stores visible

            uint32_t aBase[2], bBase[4];
#pragma unroll
            for (int mt = 0; mt < 2; mt++)
                aBase[mt] = s2u(&Ps[wm*32 + mt*16 + lr][kc*64 + lc]);
#pragma unroll
            for (int np = 0; np < 4; np++)
                bBase[np] = s2u(&KV[kc][wq4*64 + np*16 + lr][lc]);

#pragma unroll
            for (int kt = 0; kt < 64; kt += 16) {
                uint32_t af[2][4], bm[4][4];
#pragma unroll
                for (int mt = 0; mt < 2; mt++) ldsm4(af[mt], aBase[mt] + kt*2);
#pragma unroll
                for (int np = 0; np < 4; np++) ldsm4(bm[np], bBase[np] + kt*2);
#pragma unroll
                for (int mt = 0; mt < 2; mt++)
#pragma unroll
                    for (int nt = 0; nt < 8; nt++) {
                        uint32_t bfr[2] = { bm[nt>>1][nt & 1], bm[nt>>1][(nt & 1) + 2] };
                        mma16(acc_o[mt][nt], af[mt], bfr);
                    }
            }
            __syncthreads();   // protect KV/Ps for next phase/iter
        }
    }

    // ---------------- epilogue: O / l_run -----------------------------------
    float inv[2][2];
#pragma unroll
    for (int mt = 0; mt < 2; mt++)
#pragma unroll
        for (int h = 0; h < 2; h++)
            inv[mt][h] = 1.f / l_run[mt][h];

#pragma unroll
    for (int mt = 0; mt < 2; mt++) {
#pragma unroll
        for (int nt = 0; nt < 8; nt++) {
            int row = m0 + wm*32 + mt*16 + g;
            int col = wq4*64 + nt*8 + 2*tg;
            float* o = acc_o[mt][nt];
            *(float2*)&O[(size_t)row*DD + col] =
                make_float2(o[0]*inv[mt][0], o[1]*inv[mt][0]);
            *(float2*)&O[(size_t)(row+8)*DD + col] =
                make_float2(o[2]*inv[mt][1], o[3]*inv[mt][1]);
        }
    }
}

// ---------------------------------------------------------------------------
extern "C" void kernel_launch(void* const* d_in, const int* in_sizes, int n_in,
                              void* d_out, int out_size) {
    (void)in_sizes; (void)n_in; (void)out_size;
    const float* query = (const float*)d_in[0];
    const float* aw    = (const float*)d_in[1];
    const float* wq    = (const float*)d_in[2];
    const float* wk    = (const float*)d_in[3];
    const float* wv    = (const float*)d_in[4];
    const float* bq    = (const float*)d_in[5];
    const float* bk    = (const float*)d_in[6];
    const float* bv    = (const float*)d_in[7];
    float* out = (float*)d_out;

    cudaFuncSetAttribute(proj_bf,  cudaFuncAttributeMaxDynamicSharedMemorySize, GEMM_SMEM);
    cudaFuncSetAttribute(flash_bf, cudaFuncAttributeMaxDynamicSharedMemorySize, FLASH_SMEM);

    wt_kernel<<<dim3(8, 8, 3*CC), dim3(32, 8)>>>(wq, wk, wv);
    int n_ctx = BB*PP*DD;
    ctx_kernel<<<(n_ctx + 255)/256, 256>>>(query, aw);
    proj_bf<<<dim3(DD/128, PP/128, 3*BB*CC), 256, GEMM_SMEM>>>(bq, bk, bv);
    vt_kernel<<<dim3(DD/32, PP/32, BB*CC), dim3(32, 8)>>>();
    flash_bf<<<dim3(PP/128, BB*CC), 512, FLASH_SMEM>>>(out);
}